// round 12
// baseline (speedup 1.0000x reference)
#include <cuda_runtime.h>
#include <cstddef>
#include <cstdint>

#define NSEL      20000
#define NB        32      // batch rows
#define IP        128     // in planes (K)
#define OP        32      // hidden planes (N)
#define CK        32      // K-chunk (floats) for w0
#define XP        132     // xs row pitch (132 mod 32 = 4 -> conflict-free frags)
#define WP        40      // ws row pitch -> conflict-free B frags
#define NTHREADS  128

__device__ __forceinline__ uint32_t smem_u32(const void* p) {
    uint32_t a;
    asm("{ .reg .u64 t; cvta.to.shared.u64 t, %1; cvt.u32.u64 %0, t; }"
        : "=r"(a) : "l"(p));
    return a;
}
__device__ __forceinline__ void cp_async16(uint32_t dst, const void* src) {
    asm volatile("cp.async.cg.shared.global [%0], [%1], 16;\n" :: "r"(dst), "l"(src));
}
__device__ __forceinline__ void cp_async_commit() {
    asm volatile("cp.async.commit_group;\n" ::: "memory");
}
template <int N>
__device__ __forceinline__ void cp_async_wait() {
    asm volatile("cp.async.wait_group %0;\n" :: "n"(N) : "memory");
}
__device__ __forceinline__ void mma_tf32(float* d, const uint32_t* a,
                                         uint32_t b0, uint32_t b1) {
    asm("mma.sync.aligned.m16n8k8.row.col.f32.tf32.tf32.f32 "
        "{%0,%1,%2,%3}, {%4,%5,%6,%7}, {%8,%9}, {%0,%1,%2,%3};"
        : "+f"(d[0]), "+f"(d[1]), "+f"(d[2]), "+f"(d[3])
        : "r"(a[0]), "r"(a[1]), "r"(a[2]), "r"(a[3]), "r"(b0), "r"(b1));
}

__global__ __launch_bounds__(NTHREADS, 5)
void voxel_mlp_kernel(
    const float* __restrict__ x,       // [32, 20000, 128]
    const int*   __restrict__ vidx,    // [20000]
    const float* __restrict__ w0,      // [40000, 128, 32]
    const float* __restrict__ b0,      // [40000, 32]
    const float* __restrict__ w1,      // [40000, 32]
    const float* __restrict__ b1,      // [40000]
    float*       __restrict__ out)     // [32, 20000]
{
    __shared__ float xs[NB * XP];          // 16.9 KB, whole x tile
    __shared__ float ws[4][CK * WP];       // 20.5 KB, all 4 w0 chunks
    __shared__ float b0s[OP];
    __shared__ float w1s[OP];
    __shared__ float b1s;
    __shared__ float pwork[2][NB];

    const int n  = blockIdx.x;
    const int t  = threadIdx.x;
    const int vi = __ldg(vidx + n);

    const uint32_t xs_base = smem_u32(xs);
    const uint32_t ws_base = smem_u32(ws);

    const float4* gx = (const float4*)x;                         // [b][n][32 f4]
    const float4* gw = (const float4*)w0 + (size_t)vi * (IP * OP / 4);

    // ---- group 0: whole x tile, one warp = one full 512 B row ----
    #pragma unroll
    for (int s = 0; s < 8; ++s) {
        int q  = t + NTHREADS * s;        // 0..1023
        int b  = q >> 5;                  // row 0..31 (lane sweep = full row)
        int f4 = q & 31;
        cp_async16(xs_base + (uint32_t)(b * XP + 4 * f4) * 4,
                   gx + (size_t)(b * NSEL + n) * (IP / 4) + f4);
    }
    // chunk 0 of w0 rides in group 0
    #pragma unroll
    for (int s = 0; s < 2; ++s) {
        int q  = t + NTHREADS * s;        // 0..255
        int kr = q >> 3;
        int f4 = q & 7;
        cp_async16(ws_base + (uint32_t)(0 * CK * WP + kr * WP + 4 * f4) * 4,
                   gw + q);
    }
    cp_async_commit();

    // ---- groups 1..3: w0 chunks 1..3 (contiguous 4 KB each) ----
    #pragma unroll
    for (int c = 1; c < 4; ++c) {
        #pragma unroll
        for (int s = 0; s < 2; ++s) {
            int q  = t + NTHREADS * s;
            int kr = q >> 3;
            int f4 = q & 7;
            cp_async16(ws_base + (uint32_t)(c * CK * WP + kr * WP + 4 * f4) * 4,
                       gw + c * (CK * OP / 4) + q);
        }
        cp_async_commit();
    }

    // per-voxel params (plain loads; visible after the first __syncthreads)
    if (t < OP) {
        b0s[t] = b0[(size_t)vi * OP + t];
        w1s[t] = w1[(size_t)vi * OP + t];
    }
    if (t == 0) b1s = b1[vi];

    // warp tiling: 4 warps -> (m 2) x (n 2), each warp m16 x n16
    const int wid   = t >> 5;
    const int lane  = t & 31;
    const int g     = lane >> 2;
    const int tc    = lane & 3;
    const int m_off = (wid & 1) * 16;
    const int n_off = (wid >> 1) * 16;
    const int nhalf = wid >> 1;

    const uint32_t HIMASK = 0xFFFFE000u;
    const float inv128 = 0.0078125f;
    const float inv32  = 0.03125f;

    float acc[2][4];
    #pragma unroll
    for (int ti = 0; ti < 2; ++ti)
        #pragma unroll
        for (int r = 0; r < 4; ++r) acc[ti][r] = 0.f;

    #pragma unroll
    for (int c = 0; c < 4; ++c) {
        // need groups 0..c complete; allow 3-c younger groups pending
        if      (c == 0) cp_async_wait<3>();
        else if (c == 1) cp_async_wait<2>();
        else if (c == 2) cp_async_wait<1>();
        else             cp_async_wait<0>();
        __syncthreads();

        const float* wb = &ws[c][0];
        const int    k0 = c * CK;          // global k base of this chunk

        #pragma unroll
        for (int ks = 0; ks < CK / 8; ++ks) {
            const int kk = ks * 8;

            float af[4];
            af[0] = xs[(m_off + g)     * XP + k0 + kk + tc];
            af[1] = xs[(m_off + g + 8) * XP + k0 + kk + tc];
            af[2] = xs[(m_off + g)     * XP + k0 + kk + tc + 4];
            af[3] = xs[(m_off + g + 8) * XP + k0 + kk + tc + 4];

            uint32_t ah[4], al[4];
            #pragma unroll
            for (int r = 0; r < 4; ++r) {
                ah[r] = __float_as_uint(af[r]) & HIMASK;
                al[r] = __float_as_uint(af[r] - __uint_as_float(ah[r]));
            }

            #pragma unroll
            for (int ti = 0; ti < 2; ++ti) {
                const int nb = n_off + 8 * ti + g;
                float bf0 = wb[(kk + tc)     * WP + nb];
                float bf1 = wb[(kk + tc + 4) * WP + nb];
                uint32_t bh0 = __float_as_uint(bf0) & HIMASK;
                uint32_t bl0 = __float_as_uint(bf0 - __uint_as_float(bh0));
                uint32_t bh1 = __float_as_uint(bf1) & HIMASK;
                uint32_t bl1 = __float_as_uint(bf1 - __uint_as_float(bh1));

                mma_tf32(acc[ti], ah, bh0, bh1);   // hi*hi
                mma_tf32(acc[ti], al, bh0, bh1);   // lo*hi
                mma_tf32(acc[ti], ah, bl0, bl1);   // hi*lo
            }
        }
        // no buffer reuse -> no trailing barrier needed
    }

    // ---- epilogue: scale, bias, exact-erf GELU, layer-1 projection ----
    float pr[2] = {0.f, 0.f};
    #pragma unroll
    for (int ti = 0; ti < 2; ++ti) {
        const int c0 = n_off + 8 * ti + 2 * tc;
        #pragma unroll
        for (int r = 0; r < 4; ++r) {
            const int o = c0 + (r & 1);
            float v = acc[ti][r] * inv128 + b0s[o];
            float ge = 0.5f * v * (1.f + erff(v * 0.70710678118654752f));
            pr[r >> 1] = fmaf(ge, w1s[o], pr[r >> 1]);
        }
    }
    #pragma unroll
    for (int off = 1; off < 4; off <<= 1) {
        pr[0] += __shfl_xor_sync(0xffffffffu, pr[0], off);
        pr[1] += __shfl_xor_sync(0xffffffffu, pr[1], off);
    }
    if (tc == 0) {
        pwork[nhalf][m_off + g]     = pr[0];
        pwork[nhalf][m_off + g + 8] = pr[1];
    }
    __syncthreads();

    if (t < NB)
        out[(size_t)t * NSEL + n] = (pwork[0][t] + pwork[1][t]) * inv32 + b1s;
}

extern "C" void kernel_launch(void* const* d_in, const int* in_sizes, int n_in,
                              void* d_out, int out_size)
{
    const float* x    = (const float*)d_in[0];
    const int*   vidx = (const int*)  d_in[1];
    const float* w0   = (const float*)d_in[2];
    const float* b0   = (const float*)d_in[3];
    const float* w1   = (const float*)d_in[4];
    const float* b1   = (const float*)d_in[5];
    float* out = (float*)d_out;

    voxel_mlp_kernel<<<NSEL, NTHREADS>>>(x, vidx, w0, b0, w1, b1, out);
}

// round 13
// speedup vs baseline: 1.0594x; 1.0594x over previous
#include <cuda_runtime.h>
#include <cstddef>
#include <cstdint>

#define NSEL      20000
#define NB        32      // batch rows
#define IP        128     // in planes (K)
#define OP        32      // hidden planes (N)
#define CK        32      // K-chunk (floats)
#define XP        36      // xs row pitch -> conflict-free A frags
#define WP        40      // ws row pitch -> conflict-free B frags
#define NTHREADS  128

__device__ __forceinline__ uint32_t smem_u32(const void* p) {
    uint32_t a;
    asm("{ .reg .u64 t; cvta.to.shared.u64 t, %1; cvt.u32.u64 %0, t; }"
        : "=r"(a) : "l"(p));
    return a;
}
__device__ __forceinline__ uint64_t mk_policy_evict_first() {
    uint64_t p;
    asm("createpolicy.fractional.L2::evict_first.b64 %0, 1.0;" : "=l"(p));
    return p;
}
__device__ __forceinline__ uint64_t mk_policy_evict_last() {
    uint64_t p;
    asm("createpolicy.fractional.L2::evict_last.b64 %0, 1.0;" : "=l"(p));
    return p;
}
__device__ __forceinline__ void cp_async16_pol(uint32_t dst, const void* src,
                                               uint64_t pol) {
    asm volatile("cp.async.cg.shared.global.L2::cache_hint [%0], [%1], 16, %2;\n"
                 :: "r"(dst), "l"(src), "l"(pol));
}
__device__ __forceinline__ void cp_async_commit() {
    asm volatile("cp.async.commit_group;\n" ::: "memory");
}
template <int N>
__device__ __forceinline__ void cp_async_wait() {
    asm volatile("cp.async.wait_group %0;\n" :: "n"(N) : "memory");
}
__device__ __forceinline__ void mma_tf32(float* d, const uint32_t* a,
                                         uint32_t b0, uint32_t b1) {
    asm("mma.sync.aligned.m16n8k8.row.col.f32.tf32.tf32.f32 "
        "{%0,%1,%2,%3}, {%4,%5,%6,%7}, {%8,%9}, {%0,%1,%2,%3};"
        : "+f"(d[0]), "+f"(d[1]), "+f"(d[2]), "+f"(d[3])
        : "r"(a[0]), "r"(a[1]), "r"(a[2]), "r"(a[3]), "r"(b0), "r"(b1));
}

__global__ __launch_bounds__(NTHREADS, 10)
void voxel_mlp_kernel(
    const float* __restrict__ x,       // [32, 20000, 128]
    const int*   __restrict__ vidx,    // [20000]
    const float* __restrict__ w0,      // [40000, 128, 32]
    const float* __restrict__ b0,      // [40000, 32]
    const float* __restrict__ w1,      // [40000, 32]
    const float* __restrict__ b1,      // [40000]
    float*       __restrict__ out)     // [32, 20000]
{
    __shared__ float xs[2][NB * XP];    // 9.2 KB
    __shared__ float ws[2][CK * WP];    // 10.2 KB
    __shared__ float b0s[OP];
    __shared__ float w1s[OP];
    __shared__ float outbuf[NB];
    __shared__ float b1s;

    const int n  = blockIdx.x;
    const int t  = threadIdx.x;
    const int vi = __ldg(vidx + n);

    const uint64_t pol_x = mk_policy_evict_first();  // x: streaming, no reuse
    const uint64_t pol_w = mk_policy_evict_last();   // w0: duplicate gathers

    const float4* gx = (const float4*)x;                        // [b][n][32 f4]
    const float4* gw = (const float4*)w0 + (size_t)vi * (IP * OP / 4);

    const uint32_t xs_base = smem_u32(xs);
    const uint32_t ws_base = smem_u32(ws);

    auto load_chunk = [&](int c, int buf) {
        #pragma unroll
        for (int s = 0; s < 2; ++s) {
            int q  = t + NTHREADS * s;        // 0..255
            int b  = q >> 3;                  // batch row 0..31
            int f4 = q & 7;
            cp_async16_pol(xs_base + (uint32_t)(buf * NB * XP + b * XP + 4 * f4) * 4,
                           gx + (size_t)(b * NSEL + n) * (IP / 4) + c * (CK / 4) + f4,
                           pol_x);
        }
        #pragma unroll
        for (int s = 0; s < 2; ++s) {
            int q  = t + NTHREADS * s;        // 0..255
            int kr = q >> 3;
            int f4 = q & 7;
            cp_async16_pol(ws_base + (uint32_t)(buf * CK * WP + kr * WP + 4 * f4) * 4,
                           gw + c * (CK * OP / 4) + q,
                           pol_w);
        }
        cp_async_commit();
    };

    load_chunk(0, 0);

    if (t < OP) {
        b0s[t] = b0[(size_t)vi * OP + t];
        w1s[t] = w1[(size_t)vi * OP + t];
        outbuf[t] = 0.f;
    }
    if (t == 0) b1s = b1[vi];

    load_chunk(1, 1);

    // warp tiling: 4 warps -> (m 2) x (n 2), each warp m16 x n16
    const int wid   = t >> 5;
    const int lane  = t & 31;
    const int g     = lane >> 2;      // groupID 0..7
    const int tc    = lane & 3;       // threadID in group
    const int m_off = (wid & 1) * 16;
    const int n_off = (wid >> 1) * 16;

    float acc[2][4];
    #pragma unroll
    for (int ti = 0; ti < 2; ++ti)
        #pragma unroll
        for (int r = 0; r < 4; ++r) acc[ti][r] = 0.f;

    const uint32_t HIMASK = 0xFFFFE000u;

    #pragma unroll
    for (int ch = 0; ch < IP / CK; ++ch) {
        const int buf = ch & 1;
        if (ch + 2 < IP / CK + 1) {
            // keep one younger group pending while chunk `ch` is consumed
        }
        if (ch < IP / CK - 1) cp_async_wait<1>();
        else                  cp_async_wait<0>();
        __syncthreads();

        const float* xb = &xs[buf][0];
        const float* wb = &ws[buf][0];

        #pragma unroll
        for (int ks = 0; ks < CK / 8; ++ks) {
            const int kk = ks * 8;

            float af[4];
            af[0] = xb[(m_off + g)     * XP + kk + tc];
            af[1] = xb[(m_off + g + 8) * XP + kk + tc];
            af[2] = xb[(m_off + g)     * XP + kk + tc + 4];
            af[3] = xb[(m_off + g + 8) * XP + kk + tc + 4];

            uint32_t ah[4], al[4];
            #pragma unroll
            for (int r = 0; r < 4; ++r) {
                ah[r] = __float_as_uint(af[r]) & HIMASK;
                al[r] = __float_as_uint(af[r] - __uint_as_float(ah[r]));
            }

            #pragma unroll
            for (int ti = 0; ti < 2; ++ti) {
                const int nb = n_off + 8 * ti + g;
                float bf0 = wb[(kk + tc)     * WP + nb];
                float bf1 = wb[(kk + tc + 4) * WP + nb];
                uint32_t bh0 = __float_as_uint(bf0) & HIMASK;
                uint32_t bl0 = __float_as_uint(bf0 - __uint_as_float(bh0));
                uint32_t bh1 = __float_as_uint(bf1) & HIMASK;
                uint32_t bl1 = __float_as_uint(bf1 - __uint_as_float(bh1));

                mma_tf32(acc[ti], ah, bh0, bh1);   // hi*hi
                mma_tf32(acc[ti], al, bh0, bh1);   // lo*hi
                mma_tf32(acc[ti], ah, bl0, bl1);   // hi*lo
            }
        }
        __syncthreads();   // all reads of buf done before refill

        if (ch + 2 < IP / CK)
            load_chunk(ch + 2, buf);
    }

    // ---- epilogue: scale, bias, exact-erf GELU, layer-1 projection ----
    const float inv128 = 0.0078125f;
    const float inv32  = 0.03125f;

    float pr[2] = {0.f, 0.f};   // rows m_off+g and m_off+g+8
    #pragma unroll
    for (int ti = 0; ti < 2; ++ti) {
        const int c0 = n_off + 8 * ti + 2 * tc;
        #pragma unroll
        for (int r = 0; r < 4; ++r) {
            const int o = c0 + (r & 1);
            float v = acc[ti][r] * inv128 + b0s[o];
            float ge = 0.5f * v * (1.f + erff(v * 0.70710678118654752f));
            pr[r >> 1] = fmaf(ge, w1s[o], pr[r >> 1]);
        }
    }
    #pragma unroll
    for (int off = 1; off < 4; off <<= 1) {
        pr[0] += __shfl_xor_sync(0xffffffffu, pr[0], off);
        pr[1] += __shfl_xor_sync(0xffffffffu, pr[1], off);
    }
    if (tc == 0) {
        atomicAdd(&outbuf[m_off + g],     pr[0]);
        atomicAdd(&outbuf[m_off + g + 8], pr[1]);
    }
    __syncthreads();

    if (t < NB)
        out[(size_t)t * NSEL + n] = outbuf[t] * inv32 + b1s;
}

extern "C" void kernel_launch(void* const* d_in, const int* in_sizes, int n_in,
                              void* d_out, int out_size)
{
    const float* x    = (const float*)d_in[0];
    const int*   vidx = (const int*)  d_in[1];
    const float* w0   = (const float*)d_in[2];
    const float* b0   = (const float*)d_in[3];
    const float* w1   = (const float*)d_in[4];
    const float* b1   = (const float*)d_in[5];
    float* out = (float*)d_out;

    voxel_mlp_kernel<<<NSEL, NTHREADS>>>(x, vidx, w0, b0, w1, b1, out);
}

// round 14
// speedup vs baseline: 1.0619x; 1.0024x over previous
#include <cuda_runtime.h>
#include <cstddef>
#include <cstdint>

#define NSEL      20000
#define NB        32      // batch rows
#define IP        128     // in planes (K)
#define OP        32      // hidden planes (N)
#define CK        32      // K-chunk (floats)
#define XP        36      // xs row pitch -> conflict-free A frags
#define WP        40      // ws row pitch -> conflict-free B frags
#define NTHREADS  128

__device__ __forceinline__ uint32_t smem_u32(const void* p) {
    uint32_t a;
    asm("{ .reg .u64 t; cvta.to.shared.u64 t, %1; cvt.u32.u64 %0, t; }"
        : "=r"(a) : "l"(p));
    return a;
}
__device__ __forceinline__ uint64_t mk_policy_evict_first() {
    uint64_t p;
    asm("createpolicy.fractional.L2::evict_first.b64 %0, 1.0;" : "=l"(p));
    return p;
}
__device__ __forceinline__ uint64_t mk_policy_evict_last() {
    uint64_t p;
    asm("createpolicy.fractional.L2::evict_last.b64 %0, 1.0;" : "=l"(p));
    return p;
}
__device__ __forceinline__ void cp_async16_pol(uint32_t dst, const void* src,
                                               uint64_t pol) {
    asm volatile("cp.async.cg.shared.global.L2::cache_hint [%0], [%1], 16, %2;\n"
                 :: "r"(dst), "l"(src), "l"(pol));
}
__device__ __forceinline__ void cp_async_commit() {
    asm volatile("cp.async.commit_group;\n" ::: "memory");
}
template <int N>
__device__ __forceinline__ void cp_async_wait() {
    asm volatile("cp.async.wait_group %0;\n" :: "n"(N) : "memory");
}
__device__ __forceinline__ void mma_tf32(float* d, const uint32_t* a,
                                         uint32_t b0, uint32_t b1) {
    asm("mma.sync.aligned.m16n8k8.row.col.f32.tf32.tf32.f32 "
        "{%0,%1,%2,%3}, {%4,%5,%6,%7}, {%8,%9}, {%0,%1,%2,%3};"
        : "+f"(d[0]), "+f"(d[1]), "+f"(d[2]), "+f"(d[3])
        : "r"(a[0]), "r"(a[1]), "r"(a[2]), "r"(a[3]), "r"(b0), "r"(b1));
}

__global__ __launch_bounds__(NTHREADS, 10)
void voxel_mlp_kernel(
    const float* __restrict__ x,       // [32, 20000, 128]
    const int*   __restrict__ vidx,    // [20000]
    const float* __restrict__ w0,      // [40000, 128, 32]
    const float* __restrict__ b0,      // [40000, 32]
    const float* __restrict__ w1,      // [40000, 32]
    const float* __restrict__ b1,      // [40000]
    float*       __restrict__ out)     // [32, 20000]
{
    __shared__ float xs[2][NB * XP];    // 9.2 KB
    __shared__ float ws[2][CK * WP];    // 10.2 KB
    __shared__ float b0s[OP];
    __shared__ float w1s[OP];
    __shared__ float outbuf[NB];
    __shared__ float b1s;

    const int n  = blockIdx.x;
    const int t  = threadIdx.x;
    const int vi = __ldg(vidx + n);

    const uint64_t pol_x = mk_policy_evict_first();  // x: streaming, no reuse
    const uint64_t pol_w = mk_policy_evict_last();   // w0: duplicate gathers

    const float4* gx = (const float4*)x;                        // [b][n][32 f4]
    const float4* gw = (const float4*)w0 + (size_t)vi * (IP * OP / 4);

    const uint32_t xs_base = smem_u32(xs);
    const uint32_t ws_base = smem_u32(ws);

    auto load_chunk = [&](int c, int buf) {
        #pragma unroll
        for (int s = 0; s < 2; ++s) {
            int q  = t + NTHREADS * s;        // 0..255
            int b  = q >> 3;                  // batch row 0..31
            int f4 = q & 7;
            cp_async16_pol(xs_base + (uint32_t)(buf * NB * XP + b * XP + 4 * f4) * 4,
                           gx + (size_t)(b * NSEL + n) * (IP / 4) + c * (CK / 4) + f4,
                           pol_x);
        }
        #pragma unroll
        for (int s = 0; s < 2; ++s) {
            int q  = t + NTHREADS * s;        // 0..255
            int kr = q >> 3;
            int f4 = q & 7;
            cp_async16_pol(ws_base + (uint32_t)(buf * CK * WP + kr * WP + 4 * f4) * 4,
                           gw + c * (CK * OP / 4) + q,
                           pol_w);
        }
        cp_async_commit();
    };

    load_chunk(0, 0);

    if (t < OP) {
        b0s[t] = b0[(size_t)vi * OP + t];
        w1s[t] = w1[(size_t)vi * OP + t];
        outbuf[t] = 0.f;
    }
    if (t == 0) b1s = b1[vi];

    load_chunk(1, 1);

    // warp tiling: 4 warps -> (m 2) x (n 2), each warp m16 x n16
    const int wid   = t >> 5;
    const int lane  = t & 31;
    const int g     = lane >> 2;      // groupID 0..7
    const int tc    = lane & 3;       // threadID in group
    const int m_off = (wid & 1) * 16;
    const int n_off = (wid >> 1) * 16;

    float acc[2][4];
    #pragma unroll
    for (int ti = 0; ti < 2; ++ti)
        #pragma unroll
        for (int r = 0; r < 4; ++r) acc[ti][r] = 0.f;

    const uint32_t HIMASK = 0xFFFFE000u;

    #pragma unroll
    for (int ch = 0; ch < IP / CK; ++ch) {
        const int buf = ch & 1;
        if (ch + 2 < IP / CK + 1) {
            // keep one younger group pending while chunk `ch` is consumed
        }
        if (ch < IP / CK - 1) cp_async_wait<1>();
        else                  cp_async_wait<0>();
        __syncthreads();

        const float* xb = &xs[buf][0];
        const float* wb = &ws[buf][0];

        #pragma unroll
        for (int ks = 0; ks < CK / 8; ++ks) {
            const int kk = ks * 8;

            float af[4];
            af[0] = xb[(m_off + g)     * XP + kk + tc];
            af[1] = xb[(m_off + g + 8) * XP + kk + tc];
            af[2] = xb[(m_off + g)     * XP + kk + tc + 4];
            af[3] = xb[(m_off + g + 8) * XP + kk + tc + 4];

            uint32_t ah[4], al[4];
            #pragma unroll
            for (int r = 0; r < 4; ++r) {
                ah[r] = __float_as_uint(af[r]) & HIMASK;
                al[r] = __float_as_uint(af[r] - __uint_as_float(ah[r]));
            }

            #pragma unroll
            for (int ti = 0; ti < 2; ++ti) {
                const int nb = n_off + 8 * ti + g;
                float bf0 = wb[(kk + tc)     * WP + nb];
                float bf1 = wb[(kk + tc + 4) * WP + nb];
                uint32_t bh0 = __float_as_uint(bf0) & HIMASK;
                uint32_t bl0 = __float_as_uint(bf0 - __uint_as_float(bh0));
                uint32_t bh1 = __float_as_uint(bf1) & HIMASK;
                uint32_t bl1 = __float_as_uint(bf1 - __uint_as_float(bh1));

                mma_tf32(acc[ti], ah, bh0, bh1);   // hi*hi
                mma_tf32(acc[ti], al, bh0, bh1);   // lo*hi
                mma_tf32(acc[ti], ah, bl0, bl1);   // hi*lo
            }
        }
        __syncthreads();   // all reads of buf done before refill

        if (ch + 2 < IP / CK)
            load_chunk(ch + 2, buf);
    }

    // ---- epilogue: scale, bias, exact-erf GELU, layer-1 projection ----
    const float inv128 = 0.0078125f;
    const float inv32  = 0.03125f;

    float pr[2] = {0.f, 0.f};   // rows m_off+g and m_off+g+8
    #pragma unroll
    for (int ti = 0; ti < 2; ++ti) {
        const int c0 = n_off + 8 * ti + 2 * tc;
        #pragma unroll
        for (int r = 0; r < 4; ++r) {
            const int o = c0 + (r & 1);
            float v = acc[ti][r] * inv128 + b0s[o];
            float ge = 0.5f * v * (1.f + erff(v * 0.70710678118654752f));
            pr[r >> 1] = fmaf(ge, w1s[o], pr[r >> 1]);
        }
    }
    #pragma unroll
    for (int off = 1; off < 4; off <<= 1) {
        pr[0] += __shfl_xor_sync(0xffffffffu, pr[0], off);
        pr[1] += __shfl_xor_sync(0xffffffffu, pr[1], off);
    }
    if (tc == 0) {
        atomicAdd(&outbuf[m_off + g],     pr[0]);
        atomicAdd(&outbuf[m_off + g + 8], pr[1]);
    }
    __syncthreads();

    if (t < NB)
        out[(size_t)t * NSEL + n] = outbuf[t] * inv32 + b1s;
}

extern "C" void kernel_launch(void* const* d_in, const int* in_sizes, int n_in,
                              void* d_out, int out_size)
{
    const float* x    = (const float*)d_in[0];
    const int*   vidx = (const int*)  d_in[1];
    const float* w0   = (const float*)d_in[2];
    const float* b0   = (const float*)d_in[3];
    const float* w1   = (const float*)d_in[4];
    const float* b1   = (const float*)d_in[5];
    float* out = (float*)d_out;

    voxel_mlp_kernel<<<NSEL, NTHREADS>>>(x, vidx, w0, b0, w1, b1, out);
}